// round 7
// baseline (speedup 1.0000x reference)
#include <cuda_runtime.h>
#include <stdint.h>

#define BB 8
#define LL 4096
#define KK 576
#define DD 4096
#define IMG_TOK 32000
#define IGNORE (-100.0f)
#define NSCAN BB                  // one scan block per batch row
#define ROWS_PER_BLK 2            // copy blocks handle 2 token rows each
#define NCOPY (BB * LL / ROWS_PER_BLK)   // 16384

// scratch: per-token code. >=0 : image feature row index (write)
//                          -1  : keep text embedding
//                          -2  : extra image placeholder -> zeros
__device__ int g_code[BB * LL];
__device__ volatile int g_row_ready[BB];   // per-batch-row flag (reset each run)
__device__ unsigned int g_done;            // completion counter (reset each run)

// ---------------------------------------------------------------------------
// Fused kernel, blockDim = 512.
//  blocks [0,8):        per-row scan; publish g_code + flag ASAP, then small outs
//  blocks [8, 8+16384): stream 2 embedding rows each, gated on the row flag
// ---------------------------------------------------------------------------
__global__ __launch_bounds__(512) void fused_kernel(
    const int*    __restrict__ input_ids,
    const int*    __restrict__ attention_mask,
    const int*    __restrict__ labels,
    const float4* __restrict__ feat,       // (B,K,D)
    const float4* __restrict__ emb,        // (B,L,D)
    float4*       __restrict__ out,        // (B,L,D)
    float*        __restrict__ out_tail)   // out + B*L*D
{
    const int bid = blockIdx.x;

    if (bid < NSCAN) {
        // ================= SCAN PATH (512 threads, 8 tokens each) =========
        const int b = bid;
        const int t = threadIdx.x;               // 0..511
        const int lane = t & 31, wid = t >> 5;   // 16 warps
        const int base = b * LL + t * 8;

        int4 ida = *(const int4*)(input_ids + base);
        int4 idb = *(const int4*)(input_ids + base + 4);

        int im[8] = { ida.x == IMG_TOK, ida.y == IMG_TOK, ida.z == IMG_TOK, ida.w == IMG_TOK,
                      idb.x == IMG_TOK, idb.y == IMG_TOK, idb.z == IMG_TOK, idb.w == IMG_TOK };
        int local = 0;
        #pragma unroll
        for (int i = 0; i < 8; i++) local += im[i];

        __shared__ int warp_sums[16];

        // ---- scan #1: image-token ranks ----
        int v = local;
        #pragma unroll
        for (int o = 1; o < 32; o <<= 1) { int n = __shfl_up_sync(~0u, v, o); if (lane >= o) v += n; }
        if (lane == 31) warp_sums[wid] = v;
        __syncthreads();
        if (wid == 0 && lane < 16) {
            int s = warp_sums[lane];
            #pragma unroll
            for (int o = 1; o < 16; o <<= 1) {
                int n = __shfl_up_sync(0xffffu, s, o); if (lane >= o) s += n;
            }
            warp_sums[lane] = s;
        }
        __syncthreads();
        int excl = (v - local) + (wid > 0 ? warp_sums[wid - 1] : 0);

        // code[] depends only on input_ids -> compute + publish FIRST
        int code[8];
        int run = excl;
        #pragma unroll
        for (int i = 0; i < 8; i++) {
            if (im[i]) { int r = run++; code[i] = (r < KK) ? r : -2; }
            else       { code[i] = -1; }
        }
        *(int4*)(g_code + base)     = make_int4(code[0], code[1], code[2], code[3]);
        *(int4*)(g_code + base + 4) = make_int4(code[4], code[5], code[6], code[7]);
        __threadfence();
        __syncthreads();
        if (t == 0) g_row_ready[b] = 1;

        // ---- remaining small outputs (overlap with copy traffic) ----
        int4 ama = *(const int4*)(attention_mask + base);
        int4 amb = *(const int4*)(attention_mask + base + 4);
        int4 lba = *(const int4*)(labels + base);
        int4 lbb = *(const int4*)(labels + base + 4);
        int am[8] = { ama.x, ama.y, ama.z, ama.w, amb.x, amb.y, amb.z, amb.w };
        int lb[8] = { lba.x, lba.y, lba.z, lba.w, lbb.x, lbb.y, lbb.z, lbb.w };

        int   fattn[8];
        float flab[8], fmask[8];
        #pragma unroll
        for (int i = 0; i < 8; i++) {
            if (im[i]) {
                fattn[i] = (code[i] >= 0) ? 1 : 0;
                fmask[i] = (code[i] >= 0) ? 1.0f : 0.0f;   // extra -> id PAD(0)
                flab[i]  = IGNORE;
            } else {
                fattn[i] = am[i];
                fmask[i] = 0.0f;
                flab[i]  = (float)lb[i];
            }
        }

        __syncthreads();   // reuse warp_sums
        // ---- scan #2: final attention mask -> position_ids ----
        int local2 = 0;
        #pragma unroll
        for (int i = 0; i < 8; i++) local2 += fattn[i];
        int v2 = local2;
        #pragma unroll
        for (int o = 1; o < 32; o <<= 1) { int n = __shfl_up_sync(~0u, v2, o); if (lane >= o) v2 += n; }
        if (lane == 31) warp_sums[wid] = v2;
        __syncthreads();
        if (wid == 0 && lane < 16) {
            int s = warp_sums[lane];
            #pragma unroll
            for (int o = 1; o < 16; o <<= 1) {
                int n = __shfl_up_sync(0xffffu, s, o); if (lane >= o) s += n;
            }
            warp_sums[lane] = s;
        }
        __syncthreads();
        int excl2 = (v2 - local2) + (wid > 0 ? warp_sums[wid - 1] : 0);

        float fpos[8];
        int csum = excl2;
        #pragma unroll
        for (int i = 0; i < 8; i++) {
            csum += fattn[i];
            int p = csum - 1;
            fpos[i] = (float)(p < 0 ? 0 : p);
        }

        const int NTOK = BB * LL;
        #pragma unroll
        for (int h = 0; h < 2; h++) {
            int o = h * 4;
            *(float4*)(out_tail + 0 * NTOK + base + o) =
                make_float4((float)fattn[o], (float)fattn[o+1], (float)fattn[o+2], (float)fattn[o+3]);
            *(float4*)(out_tail + 1 * NTOK + base + o) =
                make_float4(flab[o], flab[o+1], flab[o+2], flab[o+3]);
            *(float4*)(out_tail + 2 * NTOK + base + o) =
                make_float4(fpos[o], fpos[o+1], fpos[o+2], fpos[o+3]);
            *(float4*)(out_tail + 3 * NTOK + base + o) =
                make_float4(fmask[o], fmask[o+1], fmask[o+2], fmask[o+3]);
        }
    } else {
        // ================= COPY PATH (2 rows, 512 threads) ================
        const int base_row = (bid - NSCAN) * ROWS_PER_BLK;
        const int b = base_row >> 12;            // both rows in same batch row

        if (threadIdx.x == 0) {
            while (g_row_ready[b] == 0) __nanosleep(64);
            __threadfence();                     // acquire for g_code
        }
        __syncthreads();

        const int half = threadIdx.x >> 8;       // 0 or 1: which row
        const int tid  = threadIdx.x & 255;      // 0..255 within the row
        const int row  = base_row + half;
        const int code = g_code[row];            // COHERENT load (not __ldg!)
        const int D4   = DD / 4;                 // 1024 float4 per row

        float4* dst = out + (size_t)row * D4;

        if (code == -2) {                        // extra placeholder -> zeros
            float4 z = make_float4(0.f, 0.f, 0.f, 0.f);
            #pragma unroll
            for (int i = 0; i < 4; i++) dst[i * 256 + tid] = z;
        } else {
            const float4* src = (code >= 0)
                ? feat + ((size_t)b * KK + code) * D4
                : emb  + (size_t)row * D4;

            float4 r0 = src[0 * 256 + tid];
            float4 r1 = src[1 * 256 + tid];
            float4 r2 = src[2 * 256 + tid];
            float4 r3 = src[3 * 256 + tid];
            dst[0 * 256 + tid] = r0;
            dst[1 * 256 + tid] = r1;
            dst[2 * 256 + tid] = r2;
            dst[3 * 256 + tid] = r3;
        }
    }

    // ---- epilogue: last block resets inter-block state for next replay ----
    __syncthreads();
    if (threadIdx.x == 0) {
        __threadfence();
        unsigned t = atomicAdd(&g_done, 1);
        if (t == gridDim.x - 1) {
            #pragma unroll
            for (int i = 0; i < NSCAN; i++) g_row_ready[i] = 0;
            __threadfence();
            g_done = 0;
        }
    }
}

// ---------------------------------------------------------------------------
extern "C" void kernel_launch(void* const* d_in, const int* in_sizes, int n_in,
                              void* d_out, int out_size)
{
    const float* image_features = (const float*)d_in[0];   // (B,K,D) f32
    const float* inputs_embeds  = (const float*)d_in[1];   // (B,L,D) f32
    const int*   input_ids      = (const int*)d_in[2];     // (B,L) i32
    const int*   attention_mask = (const int*)d_in[3];     // (B,L) i32
    const int*   labels         = (const int*)d_in[4];     // (B,L) i32

    float* out = (float*)d_out;
    float* out_tail = out + (size_t)BB * LL * DD;

    fused_kernel<<<NSCAN + NCOPY, 512>>>(
        input_ids, attention_mask, labels,
        (const float4*)image_features,
        (const float4*)inputs_embeds,
        (float4*)out, out_tail);
}

// round 9
// speedup vs baseline: 1.2506x; 1.2506x over previous
#include <cuda_runtime.h>
#include <stdint.h>

#define BB 8
#define LL 4096
#define KK 576
#define DD 4096
#define IMG_TOK 32000
#define IGNORE (-100.0f)
#define NSCAN BB                 // one scan block per batch row
#define ROWS_PER_BLK 4           // copy blocks handle 4 token rows each
#define NCOPY (BB * LL / ROWS_PER_BLK)   // 8192

// scratch: per-token code. >=0 : image feature row index (write)
//                          -1  : keep text embedding
//                          -2  : extra image placeholder -> zeros
__device__ int g_code[BB * LL];
__device__ volatile int g_row_ready[BB];   // per-batch-row flag (reset each run)
__device__ unsigned int g_done;            // completion counter (reset each run)

// ---------------------------------------------------------------------------
// Fused kernel, blockDim = 1024.
//  blocks [0,8):       per-row scan (4 tokens/thread -> low regs);
//                      publish g_code + flag ASAP, then small outputs
//  blocks [8, 8+8192): stream 4 embedding rows each, gated on the row flag
// ---------------------------------------------------------------------------
__global__ __launch_bounds__(1024) void fused_kernel(
    const int*    __restrict__ input_ids,
    const int*    __restrict__ attention_mask,
    const int*    __restrict__ labels,
    const float4* __restrict__ feat,       // (B,K,D)
    const float4* __restrict__ emb,        // (B,L,D)
    float4*       __restrict__ out,        // (B,L,D)
    float*        __restrict__ out_tail)   // out + B*L*D
{
    const int bid = blockIdx.x;

    if (bid < NSCAN) {
        // ================= SCAN PATH (1024 threads, 4 tokens each) ========
        const int b = bid;
        const int t = threadIdx.x;               // 0..1023
        const int lane = t & 31, wid = t >> 5;   // 32 warps
        const int base = b * LL + t * 4;

        int4 id4 = *(const int4*)(input_ids + base);

        int im[4] = { id4.x == IMG_TOK, id4.y == IMG_TOK,
                      id4.z == IMG_TOK, id4.w == IMG_TOK };
        int local = im[0] + im[1] + im[2] + im[3];

        __shared__ int warp_sums[32];

        // ---- scan #1: image-token ranks ----
        int v = local;
        #pragma unroll
        for (int o = 1; o < 32; o <<= 1) { int n = __shfl_up_sync(~0u, v, o); if (lane >= o) v += n; }
        if (lane == 31) warp_sums[wid] = v;
        __syncthreads();
        if (wid == 0) {
            int s = warp_sums[lane];
            #pragma unroll
            for (int o = 1; o < 32; o <<= 1) { int n = __shfl_up_sync(~0u, s, o); if (lane >= o) s += n; }
            warp_sums[lane] = s;
        }
        __syncthreads();
        int excl = (v - local) + (wid > 0 ? warp_sums[wid - 1] : 0);

        // code[] depends only on input_ids -> compute + publish FIRST
        int code[4];
        int run = excl;
        #pragma unroll
        for (int i = 0; i < 4; i++) {
            if (im[i]) { int r = run++; code[i] = (r < KK) ? r : -2; }
            else       { code[i] = -1; }
        }
        *(int4*)(g_code + base) = make_int4(code[0], code[1], code[2], code[3]);
        __threadfence();
        __syncthreads();
        if (t == 0) g_row_ready[b] = 1;

        // ---- remaining small outputs (overlap with copy traffic) ----
        int4 am4 = *(const int4*)(attention_mask + base);
        int4 lb4 = *(const int4*)(labels + base);
        int am[4] = { am4.x, am4.y, am4.z, am4.w };
        int lb[4] = { lb4.x, lb4.y, lb4.z, lb4.w };

        int   fattn[4];
        float flab[4], fmask[4];
        #pragma unroll
        for (int i = 0; i < 4; i++) {
            if (im[i]) {
                fattn[i] = (code[i] >= 0) ? 1 : 0;
                fmask[i] = (code[i] >= 0) ? 1.0f : 0.0f;   // extra -> id PAD(0)
                flab[i]  = IGNORE;
            } else {
                fattn[i] = am[i];
                fmask[i] = 0.0f;
                flab[i]  = (float)lb[i];
            }
        }

        __syncthreads();   // reuse warp_sums
        // ---- scan #2: final attention mask -> position_ids ----
        int local2 = fattn[0] + fattn[1] + fattn[2] + fattn[3];
        int v2 = local2;
        #pragma unroll
        for (int o = 1; o < 32; o <<= 1) { int n = __shfl_up_sync(~0u, v2, o); if (lane >= o) v2 += n; }
        if (lane == 31) warp_sums[wid] = v2;
        __syncthreads();
        if (wid == 0) {
            int s = warp_sums[lane];
            #pragma unroll
            for (int o = 1; o < 32; o <<= 1) { int n = __shfl_up_sync(~0u, s, o); if (lane >= o) s += n; }
            warp_sums[lane] = s;
        }
        __syncthreads();
        int excl2 = (v2 - local2) + (wid > 0 ? warp_sums[wid - 1] : 0);

        float fpos[4];
        int csum = excl2;
        #pragma unroll
        for (int i = 0; i < 4; i++) {
            csum += fattn[i];
            int p = csum - 1;
            fpos[i] = (float)(p < 0 ? 0 : p);
        }

        const int NTOK = BB * LL;
        *(float4*)(out_tail + 0 * NTOK + base) =
            make_float4((float)fattn[0], (float)fattn[1], (float)fattn[2], (float)fattn[3]);
        *(float4*)(out_tail + 1 * NTOK + base) = make_float4(flab[0], flab[1], flab[2], flab[3]);
        *(float4*)(out_tail + 2 * NTOK + base) = make_float4(fpos[0], fpos[1], fpos[2], fpos[3]);
        *(float4*)(out_tail + 3 * NTOK + base) = make_float4(fmask[0], fmask[1], fmask[2], fmask[3]);
    } else {
        // ================= COPY PATH (4 rows, 1024 threads) ===============
        const int base_row = (bid - NSCAN) * ROWS_PER_BLK;   // 4 rows, same batch b
        const int b = base_row >> 12;

        if (threadIdx.x == 0) {
            while (g_row_ready[b] == 0) __nanosleep(64);
            __threadfence();            // acquire: order g_code reads after flag
        }
        __syncthreads();

        const int quarter = threadIdx.x >> 8;       // 0..3: which row
        const int tid     = threadIdx.x & 255;      // 0..255 within the row
        const int row     = base_row + quarter;
        const int code    = g_code[row];            // coherent load
        const int D4      = DD / 4;                 // 1024 float4 per row

        float4* dst = out + (size_t)row * D4;

        if (code == -2) {                           // extra placeholder -> zeros
            float4 z = make_float4(0.f, 0.f, 0.f, 0.f);
            #pragma unroll
            for (int i = 0; i < 4; i++) dst[i * 256 + tid] = z;
        } else {
            const float4* src = (code >= 0)
                ? feat + ((size_t)b * KK + code) * D4
                : emb  + (size_t)row * D4;

            float4 r0 = src[0 * 256 + tid];
            float4 r1 = src[1 * 256 + tid];
            float4 r2 = src[2 * 256 + tid];
            float4 r3 = src[3 * 256 + tid];
            dst[0 * 256 + tid] = r0;
            dst[1 * 256 + tid] = r1;
            dst[2 * 256 + tid] = r2;
            dst[3 * 256 + tid] = r3;
        }
    }

    // ---- epilogue: last block resets inter-block state for next replay ----
    __syncthreads();
    if (threadIdx.x == 0) {
        __threadfence();
        unsigned t = atomicAdd(&g_done, 1);
        if (t == gridDim.x - 1) {
            #pragma unroll
            for (int i = 0; i < NSCAN; i++) g_row_ready[i] = 0;
            __threadfence();
            g_done = 0;
        }
    }
}

// ---------------------------------------------------------------------------
extern "C" void kernel_launch(void* const* d_in, const int* in_sizes, int n_in,
                              void* d_out, int out_size)
{
    const float* image_features = (const float*)d_in[0];   // (B,K,D) f32
    const float* inputs_embeds  = (const float*)d_in[1];   // (B,L,D) f32
    const int*   input_ids      = (const int*)d_in[2];     // (B,L) i32
    const int*   attention_mask = (const int*)d_in[3];     // (B,L) i32
    const int*   labels         = (const int*)d_in[4];     // (B,L) i32

    float* out = (float*)d_out;
    float* out_tail = out + (size_t)BB * LL * DD;

    fused_kernel<<<NSCAN + NCOPY, 1024>>>(
        input_ids, attention_mask, labels,
        (const float4*)image_features,
        (const float4*)inputs_embeds,
        (float4*)out, out_tail);
}

// round 10
// speedup vs baseline: 1.2873x; 1.0293x over previous
#include <cuda_runtime.h>
#include <stdint.h>

#define BB 8
#define LL 4096
#define KK 576
#define DD 4096
#define IMG_TOK 32000
#define IGNORE (-100.0f)

#define ROWS_PER_BLK 4
#define NCOPY (BB * LL / ROWS_PER_BLK)   // 8192 copy blocks
#define CHUNK 1024                        // tokens per scan block
#define NSCANB (BB * LL / CHUNK)          // 32 scan blocks

// ---------------------------------------------------------------------------
// One kernel, all blocks fully independent (no inter-block sync, no state).
//  bid < NCOPY : stream 4 embedding rows; image-token rank computed
//                REDUNDANTLY via a cooperative prefix count (L2 broadcast).
//  bid >= NCOPY: one 1024-token chunk of the small outputs; prefix state
//                for the chunk computed the same redundant way.
// ---------------------------------------------------------------------------
__global__ __launch_bounds__(256) void fused_kernel(
    const int*    __restrict__ input_ids,
    const int*    __restrict__ attention_mask,
    const int*    __restrict__ labels,
    const float4* __restrict__ feat,       // (B,K,D)
    const float4* __restrict__ emb,        // (B,L,D)
    float4*       __restrict__ out,        // (B,L,D)
    float*        __restrict__ out_tail)   // out + B*L*D
{
    const int bid  = blockIdx.x;
    const int tid  = threadIdx.x;          // 0..255
    const int lane = tid & 31;
    const int wid  = tid >> 5;             // 8 warps

    if (bid < NCOPY) {
        // ================= COPY PATH (4 rows, 256 threads) ================
        const int base_row = bid * ROWS_PER_BLK;
        const int b  = base_row >> 12;           // batch row
        const int l0 = base_row & (LL - 1);      // local pos, multiple of 4
        const int* ids_row = input_ids + b * LL;

        // ---- cooperative count of image tokens in [0, l0) ----
        int local = 0;
        #pragma unroll
        for (int k = 0; k < 4; k++) {
            int i = (k * 256 + tid) * 4;         // covers [0, 4096)
            if (i < l0) {
                int4 v = *(const int4*)(ids_row + i);
                local += (v.x == IMG_TOK) + (v.y == IMG_TOK)
                       + (v.z == IMG_TOK) + (v.w == IMG_TOK);
            }
        }
        #pragma unroll
        for (int o = 16; o; o >>= 1) local += __shfl_down_sync(~0u, local, o);

        __shared__ int s_cnt;
        if (tid == 0) s_cnt = 0;
        __syncthreads();
        if (lane == 0 && local) atomicAdd(&s_cnt, local);
        __syncthreads();

        int run = s_cnt;                          // img tokens before l0
        int4 id4 = *(const int4*)(ids_row + l0);  // this block's 4 token ids
        int idv[4] = { id4.x, id4.y, id4.z, id4.w };

        const int D4 = DD / 4;                    // 1024 float4 per row

        // ---- stream the 4 rows ----
        #pragma unroll
        for (int r = 0; r < 4; r++) {
            int code;
            if (idv[r] == IMG_TOK) { code = (run < KK) ? run : -2; run++; }
            else                   { code = -1; }

            float4* dst = out + (size_t)(base_row + r) * D4;

            if (code == -2) {                     // extra placeholder -> zeros
                float4 z = make_float4(0.f, 0.f, 0.f, 0.f);
                #pragma unroll
                for (int i = 0; i < 4; i++) dst[i * 256 + tid] = z;
            } else {
                const float4* src = (code >= 0)
                    ? feat + ((size_t)b * KK + code) * D4
                    : emb  + (size_t)(base_row + r) * D4;
                float4 r0 = src[0 * 256 + tid];
                float4 r1 = src[1 * 256 + tid];
                float4 r2 = src[2 * 256 + tid];
                float4 r3 = src[3 * 256 + tid];
                dst[0 * 256 + tid] = r0;
                dst[1 * 256 + tid] = r1;
                dst[2 * 256 + tid] = r2;
                dst[3 * 256 + tid] = r3;
            }
        }
    } else {
        // ================= SCAN PATH (one 1024-token chunk) ===============
        const int sb    = bid - NCOPY;            // 0..31
        const int b     = sb >> 2;                // batch row
        const int chunk = sb & 3;                 // which quarter of the row
        const int cs    = chunk * CHUNK;          // chunk start (local)
        const int* ids_row = input_ids + b * LL;
        const int* am_row  = attention_mask + b * LL;

        // ---- redundant prefix over [0, cs): img count + non-img attn sum --
        int img_pre = 0, amn_pre = 0;
        for (int k = 0; k < chunk; k++) {
            int i = (k * 256 + tid) * 4;
            int4 v = *(const int4*)(ids_row + i);
            int4 a = *(const int4*)(am_row + i);
            img_pre += (v.x == IMG_TOK) + (v.y == IMG_TOK)
                     + (v.z == IMG_TOK) + (v.w == IMG_TOK);
            amn_pre += (v.x == IMG_TOK ? 0 : a.x) + (v.y == IMG_TOK ? 0 : a.y)
                     + (v.z == IMG_TOK ? 0 : a.z) + (v.w == IMG_TOK ? 0 : a.w);
        }
        #pragma unroll
        for (int o = 16; o; o >>= 1) {
            img_pre += __shfl_down_sync(~0u, img_pre, o);
            amn_pre += __shfl_down_sync(~0u, amn_pre, o);
        }
        __shared__ int s_img, s_amn;
        if (tid == 0) { s_img = 0; s_amn = 0; }
        __syncthreads();
        if (lane == 0) {
            if (img_pre) atomicAdd(&s_img, img_pre);
            if (amn_pre) atomicAdd(&s_amn, amn_pre);
        }
        __syncthreads();
        const int IMG_PRE  = s_img;
        // attn prefix: writes before cs = min(img_pre, K); plus text attn sum
        const int ATTN_PRE = (IMG_PRE < KK ? IMG_PRE : KK) + s_amn;

        // ---- chunk body: 256 threads x 4 tokens ----
        const int base = b * LL + cs + tid * 4;   // global token index
        int4 id4 = *(const int4*)(input_ids + base);
        int im[4] = { id4.x == IMG_TOK, id4.y == IMG_TOK,
                      id4.z == IMG_TOK, id4.w == IMG_TOK };
        int local = im[0] + im[1] + im[2] + im[3];

        __shared__ int warp_sums[8];

        // block scan #1: in-chunk image-token ranks
        int v = local;
        #pragma unroll
        for (int o = 1; o < 32; o <<= 1) { int n = __shfl_up_sync(~0u, v, o); if (lane >= o) v += n; }
        if (lane == 31) warp_sums[wid] = v;
        __syncthreads();
        if (wid == 0 && lane < 8) {
            int s = warp_sums[lane];
            #pragma unroll
            for (int o = 1; o < 8; o <<= 1) {
                int n = __shfl_up_sync(0xffu, s, o); if (lane >= o) s += n;
            }
            warp_sums[lane] = s;
        }
        __syncthreads();
        int rank0 = IMG_PRE + (v - local) + (wid > 0 ? warp_sums[wid - 1] : 0);

        int4 am4 = *(const int4*)(attention_mask + base);
        int4 lb4 = *(const int4*)(labels + base);
        int am[4] = { am4.x, am4.y, am4.z, am4.w };
        int lb[4] = { lb4.x, lb4.y, lb4.z, lb4.w };

        int   fattn[4];
        float flab[4], fmask[4];
        int run = rank0;
        #pragma unroll
        for (int i = 0; i < 4; i++) {
            if (im[i]) {
                int wr = (run < KK); run++;
                fattn[i] = wr;
                fmask[i] = wr ? 1.0f : 0.0f;     // extra -> id PAD(0)
                flab[i]  = IGNORE;
            } else {
                fattn[i] = am[i];
                fmask[i] = 0.0f;
                flab[i]  = (float)lb[i];
            }
        }

        __syncthreads();   // reuse warp_sums
        // block scan #2: in-chunk attn cumsum -> position_ids
        int local2 = fattn[0] + fattn[1] + fattn[2] + fattn[3];
        int v2 = local2;
        #pragma unroll
        for (int o = 1; o < 32; o <<= 1) { int n = __shfl_up_sync(~0u, v2, o); if (lane >= o) v2 += n; }
        if (lane == 31) warp_sums[wid] = v2;
        __syncthreads();
        if (wid == 0 && lane < 8) {
            int s = warp_sums[lane];
            #pragma unroll
            for (int o = 1; o < 8; o <<= 1) {
                int n = __shfl_up_sync(0xffu, s, o); if (lane >= o) s += n;
            }
            warp_sums[lane] = s;
        }
        __syncthreads();
        int csum = ATTN_PRE + (v2 - local2) + (wid > 0 ? warp_sums[wid - 1] : 0);

        float fpos[4];
        #pragma unroll
        for (int i = 0; i < 4; i++) {
            csum += fattn[i];
            int p = csum - 1;
            fpos[i] = (float)(p < 0 ? 0 : p);
        }

        const int NTOK = BB * LL;
        *(float4*)(out_tail + 0 * NTOK + base) =
            make_float4((float)fattn[0], (float)fattn[1], (float)fattn[2], (float)fattn[3]);
        *(float4*)(out_tail + 1 * NTOK + base) = make_float4(flab[0], flab[1], flab[2], flab[3]);
        *(float4*)(out_tail + 2 * NTOK + base) = make_float4(fpos[0], fpos[1], fpos[2], fpos[3]);
        *(float4*)(out_tail + 3 * NTOK + base) = make_float4(fmask[0], fmask[1], fmask[2], fmask[3]);
    }
}

// ---------------------------------------------------------------------------
extern "C" void kernel_launch(void* const* d_in, const int* in_sizes, int n_in,
                              void* d_out, int out_size)
{
    const float* image_features = (const float*)d_in[0];   // (B,K,D) f32
    const float* inputs_embeds  = (const float*)d_in[1];   // (B,L,D) f32
    const int*   input_ids      = (const int*)d_in[2];     // (B,L) i32
    const int*   attention_mask = (const int*)d_in[3];     // (B,L) i32
    const int*   labels         = (const int*)d_in[4];     // (B,L) i32

    float* out = (float*)d_out;
    float* out_tail = out + (size_t)BB * LL * DD;

    fused_kernel<<<NCOPY + NSCANB, 256>>>(
        input_ids, attention_mask, labels,
        (const float4*)image_features,
        (const float4*)inputs_embeds,
        (float4*)out, out_tail);
}